// round 14
// baseline (speedup 1.0000x reference)
#include <cuda_runtime.h>
#include <cuda_bf16.h>

// P table: n_V rows of 4 floats (softmax probabilities). 100k rows = 1.6MB,
// fully L2-resident after first touch.
#define MAX_NODES 100352
#define PART_OFF  16384
#define PART_MAX  32768
#define NT        256

static __device__ float4 g_P[MAX_NODES];
static __device__ float  g_part[PART_MAX];

// ---------------------------------------------------------------------------
// Prologue: build `full` (fixed scatter + trainable rows), then row softmax.
// Reference order: fixed scatter first, trainable second -> trainable wins on
// overlap. Equivalent: trainable occupies [nFixed, nV); fixed scatter only
// lands where target < nFixed; untouched rows in [0,nFixed) stay zero.
// ---------------------------------------------------------------------------
__global__ void fill_kernel(const float4* __restrict__ trainable, int nFixed, int nV) {
    int r = blockIdx.x * blockDim.x + threadIdx.x;
    if (r >= nV) return;
    g_P[r] = (r >= nFixed) ? trainable[r - nFixed] : make_float4(0.f, 0.f, 0.f, 0.f);
}

__global__ void scatter_kernel(const float4* __restrict__ fixedp,
                               const int* __restrict__ fidx, int nFixed) {
    int i = blockIdx.x * blockDim.x + threadIdx.x;
    if (i >= nFixed) return;
    int r = fidx[i];
    if (r >= 0 && r < nFixed) g_P[r] = fixedp[i];
}

__global__ void softmax_kernel(int nV) {
    int r = blockIdx.x * blockDim.x + threadIdx.x;
    if (r >= nV) return;
    float4 v = g_P[r];
    float m  = fmaxf(fmaxf(v.x, v.y), fmaxf(v.z, v.w));
    float ex = __expf(v.x - m);
    float ey = __expf(v.y - m);
    float ez = __expf(v.z - m);
    float ew = __expf(v.w - m);
    float inv = 1.f / (ex + ey + ez + ew);
    g_P[r] = make_float4(ex * inv, ey * inv, ez * inv, ew * inv);
}

// ---------------------------------------------------------------------------
// Reductions
// ---------------------------------------------------------------------------
__device__ __forceinline__ void block_reduce_store(float acc, float* slot) {
    #pragma unroll
    for (int o = 16; o > 0; o >>= 1)
        acc += __shfl_down_sync(0xffffffffu, acc, o);
    __shared__ float ws[NT / 32];
    int lane = threadIdx.x & 31;
    int wid  = threadIdx.x >> 5;
    if (lane == 0) ws[wid] = acc;
    __syncthreads();
    if (wid == 0) {
        acc = (lane < NT / 32) ? ws[lane] : 0.f;
        #pragma unroll
        for (int o = (NT / 32) / 2; o > 0; o >>= 1)
            acc += __shfl_down_sync(0xffffffffu, acc, o);
        if (lane == 0) *slot = acc;
    }
}

__device__ __forceinline__ float edge_dot(int ia, int ib) {
    float4 a = g_P[ia];
    float4 b = g_P[ib];
    return a.x * b.x + a.y * b.y + a.z * b.z + a.w * b.w;
}

// per-triangle variable part: -4*(dab+dbc+dac) + (16/3)*sum_a Pa*Pb*Pc
__device__ __forceinline__ float tri_term(int ia, int ib, int ic) {
    float4 a = g_P[ia];
    float4 b = g_P[ib];
    float4 c = g_P[ic];
    float abx = a.x * b.x, aby = a.y * b.y, abz = a.z * b.z, abw = a.w * b.w;
    float dab = abx + aby + abz + abw;
    float dbc = b.x * c.x + b.y * c.y + b.z * c.z + b.w * c.w;
    float dac = a.x * c.x + a.y * c.y + a.z * c.z + a.w * c.w;
    float t   = abx * c.x + aby * c.y + abz * c.z + abw * c.w;
    return -4.f * (dab + dbc + dac) + (16.f / 3.f) * t;
}

// ---------------------------------------------------------------------------
// Edge kernel: each thread consumes one int4 = 2 edges (4 gathers, MLP=4).
// Per-edge variable part: -dot(Pi,Pj). Constant 2*S2 added at finalize.
// ---------------------------------------------------------------------------
__global__ void edge_kernel(const int4* __restrict__ E4, int nChunks,
                            const int* __restrict__ Eraw, long long nEdges) {
    int gid = blockIdx.x * blockDim.x + threadIdx.x;
    int stride = gridDim.x * blockDim.x;
    float acc = 0.f;
    for (int c = gid; c < nChunks; c += stride) {
        int4 e = E4[c];
        acc -= edge_dot(e.x, e.y);
        acc -= edge_dot(e.z, e.w);
    }
    if (gid == 0 && (nEdges & 1)) {
        long long base = 2 * nEdges - 2;
        acc -= edge_dot(Eraw[base], Eraw[base + 1]);
    }
    block_reduce_store(acc, &g_part[blockIdx.x]);
}

// ---------------------------------------------------------------------------
// Triangle kernel: each thread consumes 3 int4 = 4 triangles (12 gathers).
// Constant 8*S3 added at finalize.
// ---------------------------------------------------------------------------
__global__ void tri_kernel(const int4* __restrict__ T4, int nChunks,
                           const int* __restrict__ Traw, long long nTris) {
    int gid = blockIdx.x * blockDim.x + threadIdx.x;
    int stride = gridDim.x * blockDim.x;
    float acc = 0.f;
    for (int c = gid; c < nChunks; c += stride) {
        int4 A = T4[3 * c + 0];
        int4 B = T4[3 * c + 1];
        int4 C = T4[3 * c + 2];
        acc += tri_term(A.x, A.y, A.z);
        acc += tri_term(A.w, B.x, B.y);
        acc += tri_term(B.z, B.w, C.x);
        acc += tri_term(C.y, C.z, C.w);
    }
    if (gid == 0) {
        long long covered = (long long)nChunks * 4;
        for (long long t = covered; t < nTris; ++t)
            acc += tri_term(Traw[3 * t], Traw[3 * t + 1], Traw[3 * t + 2]);
    }
    block_reduce_store(acc, &g_part[PART_OFF + blockIdx.x]);
}

// ---------------------------------------------------------------------------
// Finalize: double-precision reduce of block partials + constant term.
// ---------------------------------------------------------------------------
__global__ void finalize_kernel(float* __restrict__ out, int nbE, int nbT,
                                double constTerm) {
    __shared__ double sh[NT];
    double s = 0.0;
    for (int i = threadIdx.x; i < nbE; i += NT) s += (double)g_part[i];
    for (int i = threadIdx.x; i < nbT; i += NT) s += (double)g_part[PART_OFF + i];
    sh[threadIdx.x] = s;
    __syncthreads();
    #pragma unroll
    for (int o = NT / 2; o > 0; o >>= 1) {
        if (threadIdx.x < o) sh[threadIdx.x] += sh[threadIdx.x + o];
        __syncthreads();
    }
    if (threadIdx.x == 0) out[0] = (float)(constTerm + sh[0]);
}

// ---------------------------------------------------------------------------
// Launch
// inputs: 0 trainable_params [(nV-nF)*4 f32], 1 fixed_params [nF*4 f32],
//         2 fixed_indices [nF i32], 3 simplices_2 [S2*2 i32],
//         4 simplices_3 [S3*3 i32]; output: scalar f32.
// ---------------------------------------------------------------------------
extern "C" void kernel_launch(void* const* d_in, const int* in_sizes, int n_in,
                              void* d_out, int out_size) {
    const float* trainable = (const float*)d_in[0];
    const float* fixedp    = (const float*)d_in[1];
    const int*   fidx      = (const int*)d_in[2];
    const int*   s2        = (const int*)d_in[3];
    const int*   s3        = (const int*)d_in[4];
    float*       out       = (float*)d_out;

    int nTrainRows = in_sizes[0] / 4;
    int nFixed     = in_sizes[2];
    int nV         = nFixed + nTrainRows;
    long long S2   = in_sizes[3] / 2;
    long long S3   = in_sizes[4] / 3;

    // prologue: build full matrix then softmax (in place in g_P)
    fill_kernel<<<(nV + NT - 1) / NT, NT>>>((const float4*)trainable, nFixed, nV);
    if (nFixed > 0)
        scatter_kernel<<<(nFixed + NT - 1) / NT, NT>>>((const float4*)fixedp, fidx, nFixed);
    softmax_kernel<<<(nV + NT - 1) / NT, NT>>>(nV);

    // edges: 2 per thread
    int nChunksE = (int)(S2 / 2);
    int nbE = (nChunksE + NT - 1) / NT;
    if (nbE < 1) nbE = 1;
    if (nbE > PART_OFF) nbE = PART_OFF;
    edge_kernel<<<nbE, NT>>>((const int4*)s2, nChunksE, s2, S2);

    // triangles: 4 per thread
    int nChunksT = (int)(S3 / 4);
    int nbT = (nChunksT + NT - 1) / NT;
    if (nbT < 1) nbT = 1;
    if (nbT > PART_MAX - PART_OFF) nbT = PART_MAX - PART_OFF;
    tri_kernel<<<nbT, NT>>>((const int4*)s3, nChunksT, s3, S3);

    double constTerm = 2.0 * (double)S2 + 8.0 * (double)S3;
    finalize_kernel<<<1, NT>>>(out, nbE, nbT, constTerm);
}

// round 15
// speedup vs baseline: 1.0036x; 1.0036x over previous
#include <cuda_runtime.h>
#include <cuda_bf16.h>

// P table: n_V rows of 4 floats (softmax probabilities). 100k rows = 1.6MB,
// fully L2-resident after first touch.
#define MAX_NODES 100352
#define PART_OFF  16384
#define PART_MAX  32768
#define NT        256

static __device__ float4 g_P[MAX_NODES];
static __device__ float  g_part[PART_MAX];

// ---------------------------------------------------------------------------
// Prologue: build `full` (fixed scatter + trainable rows), then row softmax.
// Reference order: fixed scatter first, trainable second -> trainable wins on
// overlap. Equivalent: trainable occupies [nFixed, nV); fixed scatter only
// lands where target < nFixed; untouched rows in [0,nFixed) stay zero.
// ---------------------------------------------------------------------------
__global__ void fill_kernel(const float4* __restrict__ trainable, int nFixed, int nV) {
    int r = blockIdx.x * blockDim.x + threadIdx.x;
    if (r >= nV) return;
    g_P[r] = (r >= nFixed) ? trainable[r - nFixed] : make_float4(0.f, 0.f, 0.f, 0.f);
}

__global__ void scatter_kernel(const float4* __restrict__ fixedp,
                               const int* __restrict__ fidx, int nFixed) {
    int i = blockIdx.x * blockDim.x + threadIdx.x;
    if (i >= nFixed) return;
    int r = fidx[i];
    if (r >= 0 && r < nFixed) g_P[r] = fixedp[i];
}

__global__ void softmax_kernel(int nV) {
    int r = blockIdx.x * blockDim.x + threadIdx.x;
    if (r >= nV) return;
    float4 v = g_P[r];
    float m  = fmaxf(fmaxf(v.x, v.y), fmaxf(v.z, v.w));
    float ex = __expf(v.x - m);
    float ey = __expf(v.y - m);
    float ez = __expf(v.z - m);
    float ew = __expf(v.w - m);
    float inv = 1.f / (ex + ey + ez + ew);
    g_P[r] = make_float4(ex * inv, ey * inv, ez * inv, ew * inv);
}

// ---------------------------------------------------------------------------
// Reductions
// ---------------------------------------------------------------------------
__device__ __forceinline__ void block_reduce_store(float acc, float* slot) {
    #pragma unroll
    for (int o = 16; o > 0; o >>= 1)
        acc += __shfl_down_sync(0xffffffffu, acc, o);
    __shared__ float ws[NT / 32];
    int lane = threadIdx.x & 31;
    int wid  = threadIdx.x >> 5;
    if (lane == 0) ws[wid] = acc;
    __syncthreads();
    if (wid == 0) {
        acc = (lane < NT / 32) ? ws[lane] : 0.f;
        #pragma unroll
        for (int o = (NT / 32) / 2; o > 0; o >>= 1)
            acc += __shfl_down_sync(0xffffffffu, acc, o);
        if (lane == 0) *slot = acc;
    }
}

__device__ __forceinline__ float edge_dot(int ia, int ib) {
    float4 a = g_P[ia];
    float4 b = g_P[ib];
    return a.x * b.x + a.y * b.y + a.z * b.z + a.w * b.w;
}

// per-triangle variable part: -4*(dab+dbc+dac) + (16/3)*sum_a Pa*Pb*Pc
__device__ __forceinline__ float tri_term(int ia, int ib, int ic) {
    float4 a = g_P[ia];
    float4 b = g_P[ib];
    float4 c = g_P[ic];
    float abx = a.x * b.x, aby = a.y * b.y, abz = a.z * b.z, abw = a.w * b.w;
    float dab = abx + aby + abz + abw;
    float dbc = b.x * c.x + b.y * c.y + b.z * c.z + b.w * c.w;
    float dac = a.x * c.x + a.y * c.y + a.z * c.z + a.w * c.w;
    float t   = abx * c.x + aby * c.y + abz * c.z + abw * c.w;
    return -4.f * (dab + dbc + dac) + (16.f / 3.f) * t;
}

// ---------------------------------------------------------------------------
// Edge kernel: each thread consumes one int4 = 2 edges (4 gathers, MLP=4).
// Per-edge variable part: -dot(Pi,Pj). Constant 2*S2 added at finalize.
// ---------------------------------------------------------------------------
__global__ void edge_kernel(const int4* __restrict__ E4, int nChunks,
                            const int* __restrict__ Eraw, long long nEdges) {
    int gid = blockIdx.x * blockDim.x + threadIdx.x;
    int stride = gridDim.x * blockDim.x;
    float acc = 0.f;
    for (int c = gid; c < nChunks; c += stride) {
        int4 e = E4[c];
        acc -= edge_dot(e.x, e.y);
        acc -= edge_dot(e.z, e.w);
    }
    if (gid == 0 && (nEdges & 1)) {
        long long base = 2 * nEdges - 2;
        acc -= edge_dot(Eraw[base], Eraw[base + 1]);
    }
    block_reduce_store(acc, &g_part[blockIdx.x]);
}

// ---------------------------------------------------------------------------
// Triangle kernel: each thread consumes 3 int4 = 4 triangles (12 gathers).
// Constant 8*S3 added at finalize.
// ---------------------------------------------------------------------------
__global__ void tri_kernel(const int4* __restrict__ T4, int nChunks,
                           const int* __restrict__ Traw, long long nTris) {
    int gid = blockIdx.x * blockDim.x + threadIdx.x;
    int stride = gridDim.x * blockDim.x;
    float acc = 0.f;
    for (int c = gid; c < nChunks; c += stride) {
        int4 A = T4[3 * c + 0];
        int4 B = T4[3 * c + 1];
        int4 C = T4[3 * c + 2];
        acc += tri_term(A.x, A.y, A.z);
        acc += tri_term(A.w, B.x, B.y);
        acc += tri_term(B.z, B.w, C.x);
        acc += tri_term(C.y, C.z, C.w);
    }
    if (gid == 0) {
        long long covered = (long long)nChunks * 4;
        for (long long t = covered; t < nTris; ++t)
            acc += tri_term(Traw[3 * t], Traw[3 * t + 1], Traw[3 * t + 2]);
    }
    block_reduce_store(acc, &g_part[PART_OFF + blockIdx.x]);
}

// ---------------------------------------------------------------------------
// Finalize: double-precision reduce of block partials + constant term.
// ---------------------------------------------------------------------------
__global__ void finalize_kernel(float* __restrict__ out, int nbE, int nbT,
                                double constTerm) {
    __shared__ double sh[NT];
    double s = 0.0;
    for (int i = threadIdx.x; i < nbE; i += NT) s += (double)g_part[i];
    for (int i = threadIdx.x; i < nbT; i += NT) s += (double)g_part[PART_OFF + i];
    sh[threadIdx.x] = s;
    __syncthreads();
    #pragma unroll
    for (int o = NT / 2; o > 0; o >>= 1) {
        if (threadIdx.x < o) sh[threadIdx.x] += sh[threadIdx.x + o];
        __syncthreads();
    }
    if (threadIdx.x == 0) out[0] = (float)(constTerm + sh[0]);
}

// ---------------------------------------------------------------------------
// Launch
// inputs: 0 trainable_params [(nV-nF)*4 f32], 1 fixed_params [nF*4 f32],
//         2 fixed_indices [nF i32], 3 simplices_2 [S2*2 i32],
//         4 simplices_3 [S3*3 i32]; output: scalar f32.
// ---------------------------------------------------------------------------
extern "C" void kernel_launch(void* const* d_in, const int* in_sizes, int n_in,
                              void* d_out, int out_size) {
    const float* trainable = (const float*)d_in[0];
    const float* fixedp    = (const float*)d_in[1];
    const int*   fidx      = (const int*)d_in[2];
    const int*   s2        = (const int*)d_in[3];
    const int*   s3        = (const int*)d_in[4];
    float*       out       = (float*)d_out;

    int nTrainRows = in_sizes[0] / 4;
    int nFixed     = in_sizes[2];
    int nV         = nFixed + nTrainRows;
    long long S2   = in_sizes[3] / 2;
    long long S3   = in_sizes[4] / 3;

    // prologue: build full matrix then softmax (in place in g_P)
    fill_kernel<<<(nV + NT - 1) / NT, NT>>>((const float4*)trainable, nFixed, nV);
    if (nFixed > 0)
        scatter_kernel<<<(nFixed + NT - 1) / NT, NT>>>((const float4*)fixedp, fidx, nFixed);
    softmax_kernel<<<(nV + NT - 1) / NT, NT>>>(nV);

    // edges: 2 per thread
    int nChunksE = (int)(S2 / 2);
    int nbE = (nChunksE + NT - 1) / NT;
    if (nbE < 1) nbE = 1;
    if (nbE > PART_OFF) nbE = PART_OFF;
    edge_kernel<<<nbE, NT>>>((const int4*)s2, nChunksE, s2, S2);

    // triangles: 4 per thread
    int nChunksT = (int)(S3 / 4);
    int nbT = (nChunksT + NT - 1) / NT;
    if (nbT < 1) nbT = 1;
    if (nbT > PART_MAX - PART_OFF) nbT = PART_MAX - PART_OFF;
    tri_kernel<<<nbT, NT>>>((const int4*)s3, nChunksT, s3, S3);

    double constTerm = 2.0 * (double)S2 + 8.0 * (double)S3;
    finalize_kernel<<<1, NT>>>(out, nbE, nbT, constTerm);
}

// round 16
// speedup vs baseline: 1.5449x; 1.5393x over previous
#include <cuda_runtime.h>
#include <cuda_bf16.h>

// P table: n_V rows of 4 floats (softmax probabilities). 100k rows = 1.6MB,
// fully L2-resident after first touch.
#define MAX_NODES 100352
#define PART_OFF  16384
#define PART_MAX  32768
#define NT        256

static __device__ float4 g_P[MAX_NODES];
static __device__ float  g_part[PART_MAX];

// ---------------------------------------------------------------------------
// Prologue: build `full` (fixed scatter + trainable rows), then row softmax.
// Reference order: fixed scatter first, trainable second -> trainable wins on
// overlap. Equivalent: trainable occupies [nFixed, nV); fixed scatter only
// lands where target < nFixed; untouched rows in [0,nFixed) stay zero.
// ---------------------------------------------------------------------------
__global__ void fill_kernel(const float4* __restrict__ trainable, int nFixed, int nV) {
    int r = blockIdx.x * blockDim.x + threadIdx.x;
    if (r >= nV) return;
    g_P[r] = (r >= nFixed) ? trainable[r - nFixed] : make_float4(0.f, 0.f, 0.f, 0.f);
}

__global__ void scatter_kernel(const float4* __restrict__ fixedp,
                               const int* __restrict__ fidx, int nFixed) {
    int i = blockIdx.x * blockDim.x + threadIdx.x;
    if (i >= nFixed) return;
    int r = fidx[i];
    if (r >= 0 && r < nFixed) g_P[r] = fixedp[i];
}

__global__ void softmax_kernel(int nV) {
    int r = blockIdx.x * blockDim.x + threadIdx.x;
    if (r >= nV) return;
    float4 v = g_P[r];
    float m  = fmaxf(fmaxf(v.x, v.y), fmaxf(v.z, v.w));
    float ex = __expf(v.x - m);
    float ey = __expf(v.y - m);
    float ez = __expf(v.z - m);
    float ew = __expf(v.w - m);
    float inv = 1.f / (ex + ey + ez + ew);
    g_P[r] = make_float4(ex * inv, ey * inv, ez * inv, ew * inv);
}

// ---------------------------------------------------------------------------
// Reductions
// ---------------------------------------------------------------------------
__device__ __forceinline__ void block_reduce_store(float acc, float* slot) {
    #pragma unroll
    for (int o = 16; o > 0; o >>= 1)
        acc += __shfl_down_sync(0xffffffffu, acc, o);
    __shared__ float ws[NT / 32];
    int lane = threadIdx.x & 31;
    int wid  = threadIdx.x >> 5;
    if (lane == 0) ws[wid] = acc;
    __syncthreads();
    if (wid == 0) {
        acc = (lane < NT / 32) ? ws[lane] : 0.f;
        #pragma unroll
        for (int o = (NT / 32) / 2; o > 0; o >>= 1)
            acc += __shfl_down_sync(0xffffffffu, acc, o);
        if (lane == 0) *slot = acc;
    }
}

__device__ __forceinline__ float edge_dot(int ia, int ib) {
    float4 a = g_P[ia];
    float4 b = g_P[ib];
    return a.x * b.x + a.y * b.y + a.z * b.z + a.w * b.w;
}

// per-triangle variable part: -4*(dab+dbc+dac) + (16/3)*sum_a Pa*Pb*Pc
__device__ __forceinline__ float tri_term(int ia, int ib, int ic) {
    float4 a = g_P[ia];
    float4 b = g_P[ib];
    float4 c = g_P[ic];
    float abx = a.x * b.x, aby = a.y * b.y, abz = a.z * b.z, abw = a.w * b.w;
    float dab = abx + aby + abz + abw;
    float dbc = b.x * c.x + b.y * c.y + b.z * c.z + b.w * c.w;
    float dac = a.x * c.x + a.y * c.y + a.z * c.z + a.w * c.w;
    float t   = abx * c.x + aby * c.y + abz * c.z + abw * c.w;
    return -4.f * (dab + dbc + dac) + (16.f / 3.f) * t;
}

// ---------------------------------------------------------------------------
// Edge kernel: each thread consumes one int4 = 2 edges (4 gathers, MLP=4).
// Per-edge variable part: -dot(Pi,Pj). Constant 2*S2 added at finalize.
// ---------------------------------------------------------------------------
__global__ void edge_kernel(const int4* __restrict__ E4, int nChunks,
                            const int* __restrict__ Eraw, long long nEdges) {
    int gid = blockIdx.x * blockDim.x + threadIdx.x;
    int stride = gridDim.x * blockDim.x;
    float acc = 0.f;
    for (int c = gid; c < nChunks; c += stride) {
        int4 e = E4[c];
        acc -= edge_dot(e.x, e.y);
        acc -= edge_dot(e.z, e.w);
    }
    if (gid == 0 && (nEdges & 1)) {
        long long base = 2 * nEdges - 2;
        acc -= edge_dot(Eraw[base], Eraw[base + 1]);
    }
    block_reduce_store(acc, &g_part[blockIdx.x]);
}

// ---------------------------------------------------------------------------
// Triangle kernel: each thread consumes 3 int4 = 4 triangles (12 gathers).
// Constant 8*S3 added at finalize.
// ---------------------------------------------------------------------------
__global__ void tri_kernel(const int4* __restrict__ T4, int nChunks,
                           const int* __restrict__ Traw, long long nTris) {
    int gid = blockIdx.x * blockDim.x + threadIdx.x;
    int stride = gridDim.x * blockDim.x;
    float acc = 0.f;
    for (int c = gid; c < nChunks; c += stride) {
        int4 A = T4[3 * c + 0];
        int4 B = T4[3 * c + 1];
        int4 C = T4[3 * c + 2];
        acc += tri_term(A.x, A.y, A.z);
        acc += tri_term(A.w, B.x, B.y);
        acc += tri_term(B.z, B.w, C.x);
        acc += tri_term(C.y, C.z, C.w);
    }
    if (gid == 0) {
        long long covered = (long long)nChunks * 4;
        for (long long t = covered; t < nTris; ++t)
            acc += tri_term(Traw[3 * t], Traw[3 * t + 1], Traw[3 * t + 2]);
    }
    block_reduce_store(acc, &g_part[PART_OFF + blockIdx.x]);
}

// ---------------------------------------------------------------------------
// Finalize: double-precision reduce of block partials + constant term.
// ---------------------------------------------------------------------------
__global__ void finalize_kernel(float* __restrict__ out, int nbE, int nbT,
                                double constTerm) {
    __shared__ double sh[NT];
    double s = 0.0;
    for (int i = threadIdx.x; i < nbE; i += NT) s += (double)g_part[i];
    for (int i = threadIdx.x; i < nbT; i += NT) s += (double)g_part[PART_OFF + i];
    sh[threadIdx.x] = s;
    __syncthreads();
    #pragma unroll
    for (int o = NT / 2; o > 0; o >>= 1) {
        if (threadIdx.x < o) sh[threadIdx.x] += sh[threadIdx.x + o];
        __syncthreads();
    }
    if (threadIdx.x == 0) out[0] = (float)(constTerm + sh[0]);
}

// ---------------------------------------------------------------------------
// Launch
// inputs: 0 trainable_params [(nV-nF)*4 f32], 1 fixed_params [nF*4 f32],
//         2 fixed_indices [nF i32], 3 simplices_2 [S2*2 i32],
//         4 simplices_3 [S3*3 i32]; output: scalar f32.
// ---------------------------------------------------------------------------
extern "C" void kernel_launch(void* const* d_in, const int* in_sizes, int n_in,
                              void* d_out, int out_size) {
    const float* trainable = (const float*)d_in[0];
    const float* fixedp    = (const float*)d_in[1];
    const int*   fidx      = (const int*)d_in[2];
    const int*   s2        = (const int*)d_in[3];
    const int*   s3        = (const int*)d_in[4];
    float*       out       = (float*)d_out;

    int nTrainRows = in_sizes[0] / 4;
    int nFixed     = in_sizes[2];
    int nV         = nFixed + nTrainRows;
    long long S2   = in_sizes[3] / 2;
    long long S3   = in_sizes[4] / 3;

    // prologue: build full matrix then softmax (in place in g_P)
    fill_kernel<<<(nV + NT - 1) / NT, NT>>>((const float4*)trainable, nFixed, nV);
    if (nFixed > 0)
        scatter_kernel<<<(nFixed + NT - 1) / NT, NT>>>((const float4*)fixedp, fidx, nFixed);
    softmax_kernel<<<(nV + NT - 1) / NT, NT>>>(nV);

    // edges: 2 per thread
    int nChunksE = (int)(S2 / 2);
    int nbE = (nChunksE + NT - 1) / NT;
    if (nbE < 1) nbE = 1;
    if (nbE > PART_OFF) nbE = PART_OFF;
    edge_kernel<<<nbE, NT>>>((const int4*)s2, nChunksE, s2, S2);

    // triangles: 4 per thread
    int nChunksT = (int)(S3 / 4);
    int nbT = (nChunksT + NT - 1) / NT;
    if (nbT < 1) nbT = 1;
    if (nbT > PART_MAX - PART_OFF) nbT = PART_MAX - PART_OFF;
    tri_kernel<<<nbT, NT>>>((const int4*)s3, nChunksT, s3, S3);

    double constTerm = 2.0 * (double)S2 + 8.0 * (double)S3;
    finalize_kernel<<<1, NT>>>(out, nbE, nbT, constTerm);
}